// round 10
// baseline (speedup 1.0000x reference)
#include <cuda_runtime.h>
#include <cstdint>

// SKA: out[b, g*32+c, h, w] = sum_{di,dj} x[b, g*32+c, h+di-2, w+dj-2] * w[b, g, di*5+dj, h, w]
// x [8,256,64,64] f32, w [8,8,25,64,64] f32, out [8,256,64,64] f32.
//
// R9 skeleton: thread = 4px x 4ch x 2rows; warp = 16wq x 2 slots; x halos via
// __shfl(width=16); w tile [25][4][64] in smem with broadcast LDS.128.
// NEW: FMA core uses Blackwell packed fma.rn.f32x2 — accumulators are 16
// packed px-pairs; each (rr,dj,c) issues 2 FFMA2 instead of 4 FFMA, halving
// FMA-pipe pressure and cutting issued instructions ~13%.

#define B_  8
#define C_  256
#define H_  64
#define W_  64
#define G_  8
#define CG_ 32
#define HW_ (H_ * W_)

__device__ __forceinline__ unsigned long long pk(float lo, float hi) {
    unsigned long long r;
    asm("mov.b64 %0, {%1, %2};" : "=l"(r) : "f"(lo), "f"(hi));
    return r;
}
__device__ __forceinline__ void fma2(unsigned long long& d,
                                     unsigned long long a,
                                     unsigned long long b) {
    asm("fma.rn.f32x2 %0, %1, %2, %0;" : "+l"(d) : "l"(a), "l"(b));
}
__device__ __forceinline__ float2 unpk(unsigned long long v) {
    float2 f;
    asm("mov.b64 {%0, %1}, %2;" : "=f"(f.x), "=f"(f.y) : "l"(v));
    return f;
}

__global__ __launch_bounds__(256, 3)
void SKA_60387240182286_kernel(const float* __restrict__ x,
                               const float* __restrict__ wgt,
                               float* __restrict__ out)
{
    __shared__ float ws[25 * 4 * W_];     // [k][4 rows][64] = 25.6 KB

    const int tid  = threadIdx.x;
    const int lane = tid & 31;
    const int warp = tid >> 5;            // 0..7
    const int wq      = lane & 15;        // 0..15: 4-wide pixel group
    const int slot_lo = lane >> 4;        // 0..1: shfl segment = channel-slot bit
    const int slot = slot_lo + 2 * (warp & 3);  // 0..7: 4-channel slot
    const int hsub = warp >> 2;           // 0..1: which hpair of the block

    const int bg  = blockIdx.x;           // b*8 + g
    const int b   = bg >> 3;
    const int g   = bg & 7;
    const int h0b = blockIdx.y * 4;       // block covers 4 output rows
    const int h0  = h0b + hsub * 2;       // this warp's 2-row base
    const int w0  = wq * 4;
    const int c0  = g * CG_ + slot * 4;

    // ---- stage w tile: rows h0b..h0b+3, all 25 taps
    {
        const float* wsrc = wgt + ((size_t)bg * 25 * H_ + h0b) * W_;
        float4* wsv = (float4*)ws;
#pragma unroll
        for (int i = tid; i < 1600; i += 256) {     // 1600 float4
            const int k   = i >> 6;                  // 64 f4 per tap (4 rows x 16)
            const int rem = i & 63;
            wsv[i] = *(const float4*)(wsrc + (size_t)k * HW_ +
                                      (rem >> 4) * W_ + (rem & 15) * 4);
        }
    }
    __syncthreads();

    const float* xb  = x + (((size_t)(b * C_ + c0)) * H_ + (h0 - 2)) * W_ + w0;
    const float* wsb = ws + (hsub * 2) * W_ + w0;   // + (k*4+rr)*W_ immediates

    // packed accumulators: [rr][c][pair]; pair0 = px{0,1}, pair1 = px{2,3}
    unsigned long long acc[2][4][2];
#pragma unroll
    for (int r = 0; r < 2; ++r)
#pragma unroll
        for (int c = 0; c < 4; ++c) {
            acc[r][c][0] = 0ULL; acc[r][c][1] = 0ULL;
        }

    const float4 z4 = make_float4(0.f, 0.f, 0.f, 0.f);
    const bool le = (wq == 0);
    const bool re = (wq == 15);

#pragma unroll
    for (int hi = 0; hi < 6; ++hi) {                // x row hy = h0 - 2 + hi
        const int hy = h0 - 2 + hi;
        const bool rv = (hy >= 0) && (hy < H_);     // warp-uniform

        // window xw[c][0..7] covers cols [w0-2 .. w0+5]
        float xw[4][8];
#pragma unroll
        for (int c = 0; c < 4; ++c) {
            const float4 m = rv ? *(const float4*)(xb + c * HW_ + hi * W_) : z4;
            const float lz = __shfl_up_sync(0xFFFFFFFFu, m.z, 1, 16);
            const float lw = __shfl_up_sync(0xFFFFFFFFu, m.w, 1, 16);
            const float rx = __shfl_down_sync(0xFFFFFFFFu, m.x, 1, 16);
            const float ry = __shfl_down_sync(0xFFFFFFFFu, m.y, 1, 16);
            xw[c][0] = le ? 0.f : lz;
            xw[c][1] = le ? 0.f : lw;
            xw[c][2] = m.x; xw[c][3] = m.y; xw[c][4] = m.z; xw[c][5] = m.w;
            xw[c][6] = re ? 0.f : rx;
            xw[c][7] = re ? 0.f : ry;
        }

        // x row hi feeds output row rr where di = hi - rr in [0,4]
#pragma unroll
        for (int dj = 0; dj < 5; ++dj) {
            // packed w taps for the (up to) 2 active output rows
            unsigned long long wp01[2], wp23[2];
            bool act[2];
#pragma unroll
            for (int rr = 0; rr < 2; ++rr) {
                const int di = hi - rr;
                act[rr] = (di >= 0) && (di <= 4);   // compile-time
                if (act[rr]) {
                    const int k = di * 5 + dj;
                    const float4 wv = *(const float4*)(wsb + (k * 4 + rr) * W_);
                    wp01[rr] = pk(wv.x, wv.y);
                    wp23[rr] = pk(wv.z, wv.w);
                }
            }
#pragma unroll
            for (int c = 0; c < 4; ++c) {
                // x pairs for this tap, shared by both output rows
                const unsigned long long xp01 = pk(xw[c][dj + 0], xw[c][dj + 1]);
                const unsigned long long xp23 = pk(xw[c][dj + 2], xw[c][dj + 3]);
#pragma unroll
                for (int rr = 0; rr < 2; ++rr) {
                    if (!act[rr]) continue;          // compile-time prune
                    fma2(acc[rr][c][0], xp01, wp01[rr]);
                    fma2(acc[rr][c][1], xp23, wp23[rr]);
                }
            }
        }
    }

    float* ob = out + (((size_t)(b * C_ + c0)) * H_ + h0) * W_ + w0;
#pragma unroll
    for (int rr = 0; rr < 2; ++rr)
#pragma unroll
        for (int c = 0; c < 4; ++c) {
            const float2 p0 = unpk(acc[rr][c][0]);
            const float2 p1 = unpk(acc[rr][c][1]);
            *(float4*)(ob + c * HW_ + rr * W_) =
                make_float4(p0.x, p0.y, p1.x, p1.y);
        }
}

extern "C" void kernel_launch(void* const* d_in, const int* in_sizes, int n_in,
                              void* d_out, int out_size)
{
    const float* x   = (const float*)d_in[0];
    const float* wgt = (const float*)d_in[1];
    float* out = (float*)d_out;

    dim3 grid(B_ * G_, H_ / 4);   // (64, 16) = 1024 blocks
    SKA_60387240182286_kernel<<<grid, 256>>>(x, wgt, out);
}